// round 15
// baseline (speedup 1.0000x reference)
#include <cuda_runtime.h>
#include <cuda_fp16.h>
#include <math.h>
#include <stdint.h>

#define BB 4
#define HH 8
#define SS 2048
#define DM 512
#define DQ 64

// ---------------------------------------------------------------- utils
__device__ __forceinline__ float ex2f(float x) {
    float y;
    asm("ex2.approx.f32 %0, %1;" : "=f"(y) : "f"(x));
    return y;
}
__device__ __forceinline__ uint32_t fh2(float a, float b) {
    __half2 h = __floats2half2_rn(a, b);
    return *reinterpret_cast<uint32_t*>(&h);
}
// D += A(16x16) @ B(16x8), fp16 inputs, fp32 accum
__device__ __forceinline__ void mma16(float d[4], const uint32_t a[4],
                                      const uint32_t b[2]) {
    asm volatile(
        "mma.sync.aligned.m16n8k16.row.col.f32.f16.f16.f32 "
        "{%0,%1,%2,%3}, {%4,%5,%6,%7}, {%8,%9}, {%0,%1,%2,%3};"
        : "+f"(d[0]), "+f"(d[1]), "+f"(d[2]), "+f"(d[3])
        : "r"(a[0]), "r"(a[1]), "r"(a[2]), "r"(a[3]), "r"(b[0]), "r"(b[1]));
}
__device__ __forceinline__ void cpasync16(uint32_t smem_addr, const void* gptr) {
    asm volatile("cp.async.cg.shared.global [%0], [%1], 16;"
                 :: "r"(smem_addr), "l"(gptr) : "memory");
}

// permuted pack of 16 logical halves into fragment order (involution):
// phys = [0,1,8,9,2,3,10,11 | 4,5,12,13,6,7,14,15]
__device__ __forceinline__ void pack16(__half* dst, const float* v) {
    __half2* d2 = reinterpret_cast<__half2*>(dst);
    d2[0] = __floats2half2_rn(v[0], v[1]);
    d2[1] = __floats2half2_rn(v[8], v[9]);
    d2[2] = __floats2half2_rn(v[2], v[3]);
    d2[3] = __floats2half2_rn(v[10], v[11]);
    d2[4] = __floats2half2_rn(v[4], v[5]);
    d2[5] = __floats2half2_rn(v[12], v[13]);
    d2[6] = __floats2half2_rn(v[6], v[7]);
    d2[7] = __floats2half2_rn(v[14], v[15]);
}

// ---------------------------------------------------------------- scratch (half)
__device__ __half g_Wqh[DM * DM];
__device__ __half g_Wkh[DM * DM];
__device__ __half g_Wvh[DM * DM];
__device__ __half g_Woh[DM * DM];
__device__ __half g_qh[BB * SS * DM];   // [b,s,h,dq] permuted-dq
__device__ __half g_kh[BB * SS * DM];
__device__ __half g_vs[BB * SS * DM];   // V projected, [b,s,h,dq] permuted-dq
__device__ __half g_vt[BB * SS * DM];   // V transposed [b][h][d][s_perm]
__device__ __half g_hh[BB * SS * DM];   // [b,h,s,dq] == concat view, permuted

// weights -> [n][k] half, k permuted; Wq scaled by 0.125*log2(e)
__global__ void prep_w(const float* __restrict__ Qw, const float* __restrict__ Kw,
                       const float* __restrict__ Vw, const float* __restrict__ Wo) {
    int idx = blockIdx.x * 256 + threadIdx.x;    // 512*32
    int n = idx >> 5;
    int grp = idx & 31;
    int hh = n >> 6, q = n & 63;
    const float SC = 0.125f * 1.4426950408889634f;
    float wq[16], wk[16], wv[16], wo[16];
#pragma unroll
    for (int l = 0; l < 16; l++) {
        int d = grp * 16 + l;
        int src = (hh * DM + d) * DQ + q;
        wq[l] = Qw[src] * SC;
        wk[l] = Kw[src];
        wv[l] = Vw[src];
        wo[l] = Wo[n * DM + d];
    }
    pack16(g_Wqh + n * DM + grp * 16, wq);
    pack16(g_Wkh + n * DM + grp * 16, wk);
    pack16(g_Wvh + n * DM + grp * 16, wv);
    pack16(g_Woh + n * DM + grp * 16, wo);
}

// ---------------------------------------------------------------- V transpose
// g_vs [b,s,h,d] -> g_vt [b][h][d][s_perm]; within-16 key perm = involution
__global__ __launch_bounds__(128) void vtrans() {
    __shared__ __half Ts[64 * 72];
    const int tid = threadIdx.x;
    const int b = blockIdx.z, h = blockIdx.y;
    const int s0 = blockIdx.x * 64;

    {
        int r = tid >> 1, seg = tid & 1;
        const uint4* src = (const uint4*)(g_vs +
            ((size_t)(b * SS + s0 + r) * HH + h) * DQ + seg * 32);
        uint4* dst = (uint4*)(Ts + r * 72 + seg * 32);
#pragma unroll
        for (int c = 0; c < 4; c++) dst[c] = src[c];
    }
    __syncthreads();

    const int PL[8] = {0, 1, 8, 9, 2, 3, 10, 11};
    const int PH[8] = {4, 5, 12, 13, 6, 7, 14, 15};
    int d = tid >> 1, dseg = tid & 1;
    __half* outp = g_vt + (((size_t)(b * HH + h)) * DQ + d) * SS + s0 + dseg * 32;
#pragma unroll
    for (int cc = 0; cc < 4; cc++) {
        int P0 = dseg * 32 + cc * 8;
        int base16 = P0 & ~15;
        __half vals[8];
#pragma unroll
        for (int p8 = 0; p8 < 8; p8++) {
            int kl = base16 + ((cc & 1) ? PH[p8] : PL[p8]);
            vals[p8] = Ts[kl * 72 + d];
        }
        *(uint4*)(outp + cc * 8) = *(const uint4*)vals;
    }
}

// ---------------------------------------------------------------- GEMM common
#define GSH 48
#define GTW (128 * GSH)
#define GE_SMEM (4 * GTW * 2)

// fused projection GEMM: A fp32 (converted+permuted on the fly), B = weights.
__global__ __launch_bounds__(256, 2) void gemm_qkv(const float* __restrict__ xq,
                                                   const float* __restrict__ xk,
                                                   const float* __restrict__ xv) {
    extern __shared__ __half sg[];
    const int z = blockIdx.z;
    const float* A = (z == 0) ? xq : (z == 1) ? xk : xv;
    const __half* B = (z == 0) ? g_Wqh : (z == 1) ? g_Wkh : g_Wvh;
    __half* C = (z == 0) ? g_qh : (z == 1) ? g_kh : g_vs;
    const int N = DM, K = DM;

    const int tid = threadIdx.x;
    const int lane = tid & 31;
    const int wid = tid >> 5;
    const int g = lane >> 2;
    const int t = lane & 3;
    const int wm = wid & 1;
    const int wn = wid >> 1;
    const int m0 = blockIdx.y * 128;
    const int n0 = blockIdx.x * 128;

    const int aRow = tid >> 1;
    const int c0 = tid & 1;

    const float* gAf = A + (size_t)(m0 + aRow) * K;
    const __half* gB = B + (size_t)(n0 + aRow) * K;

    float d[4][4][4];
#pragma unroll
    for (int i = 0; i < 4; i++)
#pragma unroll
        for (int j = 0; j < 4; j++)
#pragma unroll
            for (int c = 0; c < 4; c++) d[i][j][c] = 0.f;

    uint4 la[2], lb[2];
#pragma unroll
    for (int gi = 0; gi < 2; gi++) {
        float4 p0 = *(const float4*)(gAf + gi * 16 + c0 * 4);
        float4 p1 = *(const float4*)(gAf + gi * 16 + c0 * 4 + 8);
        la[gi] = make_uint4(fh2(p0.x, p0.y), fh2(p1.x, p1.y), fh2(p0.z, p0.w),
                            fh2(p1.z, p1.w));
    }
    lb[0] = *(const uint4*)(gB + c0 * 8);
    lb[1] = *(const uint4*)(gB + (c0 + 2) * 8);
    {
        uint4* sA = (uint4*)(sg + aRow * GSH);
        uint4* sB = (uint4*)(sg + 2 * GTW + aRow * GSH);
        sA[c0] = la[0];
        sA[c0 + 2] = la[1];
        sB[c0] = lb[0];
        sB[c0 + 2] = lb[1];
    }
    __syncthreads();

    int buf = 0;
    for (int kt = 32; kt <= K; kt += 32) {
        const bool more = (kt < K);
        if (more) {
#pragma unroll
            for (int gi = 0; gi < 2; gi++) {
                float4 p0 = *(const float4*)(gAf + kt + gi * 16 + c0 * 4);
                float4 p1 = *(const float4*)(gAf + kt + gi * 16 + c0 * 4 + 8);
                la[gi] = make_uint4(fh2(p0.x, p0.y), fh2(p1.x, p1.y),
                                    fh2(p0.z, p0.w), fh2(p1.z, p1.w));
            }
            lb[0] = *(const uint4*)(gB + kt + c0 * 8);
            lb[1] = *(const uint4*)(gB + kt + (c0 + 2) * 8);
        }

        const __half* pA = sg + buf * GTW;
        const __half* pB = sg + 2 * GTW + buf * GTW;
#pragma unroll
        for (int s = 0; s < 2; s++) {
            uint32_t a[4][4], b[4][2];
#pragma unroll
            for (int i = 0; i < 4; i++) {
                int rw = wm * 64 + i * 16 + g;
                uint2 lo = *(const uint2*)(pA + rw * GSH + s * 16 + 4 * t);
                uint2 hi = *(const uint2*)(pA + (rw + 8) * GSH + s * 16 + 4 * t);
                a[i][0] = lo.x;
                a[i][1] = hi.x;
                a[i][2] = lo.y;
                a[i][3] = hi.y;
            }
#pragma unroll
            for (int j = 0; j < 4; j++) {
                int rn = wn * 32 + j * 8 + g;
                uint2 bb = *(const uint2*)(pB + rn * GSH + s * 16 + 4 * t);
                b[j][0] = bb.x;
                b[j][1] = bb.y;
            }
#pragma unroll
            for (int i = 0; i < 4; i++)
#pragma unroll
                for (int j = 0; j < 4; j++) mma16(d[i][j], a[i], b[j]);
        }

        if (more) {
            uint4* qA = (uint4*)(sg + (buf ^ 1) * GTW + aRow * GSH);
            uint4* qB = (uint4*)(sg + 2 * GTW + (buf ^ 1) * GTW + aRow * GSH);
            qA[c0] = la[0];
            qA[c0 + 2] = la[1];
            qB[c0] = lb[0];
            qB[c0 + 2] = lb[1];
        }
        buf ^= 1;
        __syncthreads();
    }

#pragma unroll
    for (int i = 0; i < 4; i++) {
        int r0 = m0 + wm * 64 + i * 16 + g;
#pragma unroll
        for (int j = 0; j < 4; j++) {
            int colh = n0 + (wn * 2 + (j >> 1)) * 16 + 4 * t + 2 * (j & 1);
            *(uint32_t*)(C + (size_t)r0 * N + colh) = fh2(d[i][j][0], d[i][j][1]);
            *(uint32_t*)(C + (size_t)(r0 + 8) * N + colh) =
                fh2(d[i][j][2], d[i][j][3]);
        }
    }
}

// output projection: A = g_hh (half permuted), B = g_Woh, C fp32
__global__ __launch_bounds__(256, 2) void gemm_out(float* __restrict__ C) {
    extern __shared__ __half sg[];
    const __half* A = g_hh;
    const __half* B = g_Woh;
    const int N = DM, K = DM;

    const int tid = threadIdx.x;
    const int lane = tid & 31;
    const int wid = tid >> 5;
    const int g = lane >> 2;
    const int t = lane & 3;
    const int wm = wid & 1;
    const int wn = wid >> 1;
    const int m0 = blockIdx.y * 128;
    const int n0 = blockIdx.x * 128;

    const int aRow = tid >> 1;
    const int c0 = tid & 1;

    const __half* gA = A + (size_t)(m0 + aRow) * K;
    const __half* gB = B + (size_t)(n0 + aRow) * K;

    float d[4][4][4];
#pragma unroll
    for (int i = 0; i < 4; i++)
#pragma unroll
        for (int j = 0; j < 4; j++)
#pragma unroll
            for (int c = 0; c < 4; c++) d[i][j][c] = 0.f;

    uint4 la[2], lb[2];
    la[0] = *(const uint4*)(gA + c0 * 8);
    la[1] = *(const uint4*)(gA + (c0 + 2) * 8);
    lb[0] = *(const uint4*)(gB + c0 * 8);
    lb[1] = *(const uint4*)(gB + (c0 + 2) * 8);
    {
        uint4* sA = (uint4*)(sg + aRow * GSH);
        uint4* sB = (uint4*)(sg + 2 * GTW + aRow * GSH);
        sA[c0] = la[0];
        sA[c0 + 2] = la[1];
        sB[c0] = lb[0];
        sB[c0 + 2] = lb[1];
    }
    __syncthreads();

    int buf = 0;
    for (int kt = 32; kt <= K; kt += 32) {
        const bool more = (kt < K);
        if (more) {
            la[0] = *(const uint4*)(gA + kt + c0 * 8);
            la[1] = *(const uint4*)(gA + kt + (c0 + 2) * 8);
            lb[0] = *(const uint4*)(gB + kt + c0 * 8);
            lb[1] = *(const uint4*)(gB + kt + (c0 + 2) * 8);
        }

        const __half* pA = sg + buf * GTW;
        const __half* pB = sg + 2 * GTW + buf * GTW;
#pragma unroll
        for (int s = 0; s < 2; s++) {
            uint32_t a[4][4], b[4][2];
#pragma unroll
            for (int i = 0; i < 4; i++) {
                int rw = wm * 64 + i * 16 + g;
                uint2 lo = *(const uint2*)(pA + rw * GSH + s * 16 + 4 * t);
                uint2 hi = *(const uint2*)(pA + (rw + 8) * GSH + s * 16 + 4 * t);
                a[i][0] = lo.x;
                a[i][1] = hi.x;
                a[i][2] = lo.y;
                a[i][3] = hi.y;
            }
#pragma unroll
            for (int j = 0; j < 4; j++) {
                int rn = wn * 32 + j * 8 + g;
                uint2 bb = *(const uint2*)(pB + rn * GSH + s * 16 + 4 * t);
                b[j][0] = bb.x;
                b[j][1] = bb.y;
            }
#pragma unroll
            for (int i = 0; i < 4; i++)
#pragma unroll
                for (int j = 0; j < 4; j++) mma16(d[i][j], a[i], b[j]);
        }

        if (more) {
            uint4* qA = (uint4*)(sg + (buf ^ 1) * GTW + aRow * GSH);
            uint4* qB = (uint4*)(sg + 2 * GTW + (buf ^ 1) * GTW + aRow * GSH);
            qA[c0] = la[0];
            qA[c0 + 2] = la[1];
            qB[c0] = lb[0];
            qB[c0 + 2] = lb[1];
        }
        buf ^= 1;
        __syncthreads();
    }

#pragma unroll
    for (int i = 0; i < 4; i++) {
        int r0 = m0 + wm * 64 + i * 16 + g;
#pragma unroll
        for (int j = 0; j < 4; j++) {
            int cn = n0 + wn * 32 + j * 8 + t * 2;
            *(float2*)(C + (size_t)r0 * N + cn) = make_float2(d[i][j][0], d[i][j][1]);
            *(float2*)(C + (size_t)(r0 + 8) * N + cn) =
                make_float2(d[i][j][2], d[i][j][3]);
        }
    }
}

// ---------------------------------------------------------------- flash (fp16)
// CTA = (b, h, 128 query rows), 256 threads / 8 warps, warp owns 16 rows.
// cp.async double-buffered K/V tiles (2 stages): next tile's global loads
// overlap current tile's mma. Q in regs, 32-key chunks, pre-transposed V,
// skip-rescale ballot, l via ones-mma.
#define KSH 80
#define VSH 144
#define STAGE_H (128 * KSH + 64 * VSH)     // halves per stage = 19456
#define FL_SMEM (2 * STAGE_H * 2)          // 77824 B
#define ONES2 0x3C003C00u

__global__ __launch_bounds__(256, 2) void flash_h(const __half* __restrict__ qp,
                                                  const __half* __restrict__ kp,
                                                  const __half* __restrict__ vtp,
                                                  __half* __restrict__ op) {
    extern __shared__ __half sm[];

    const int tid = threadIdx.x;
    const int lane = tid & 31;
    const int wid = tid >> 5;      // 0..7
    const int g = lane >> 2;
    const int t = lane & 3;
    const int b = blockIdx.z;
    const int h = blockIdx.y;
    const int s0 = blockIdx.x * 128;
    const int rowbase = wid * 16;

    // Q fragments: one 16-row tile per warp
    const __half* gq = qp + ((size_t)(b * SS + s0) * HH + h) * DQ;
    uint32_t qa[4][4];
    {
        const __half* q0 = gq + (size_t)(rowbase + g) * DM;
        const __half* q1 = q0 + 8 * DM;
#pragma unroll
        for (int s = 0; s < 4; s++) {
            uint2 u0 = *(const uint2*)(q0 + s * 16 + 4 * t);
            uint2 u1 = *(const uint2*)(q1 + s * 16 + 4 * t);
            qa[s][0] = u0.x;
            qa[s][1] = u1.x;
            qa[s][2] = u0.y;
            qa[s][3] = u1.y;
        }
    }

    float m[2] = {-INFINITY, -INFINITY};
    float o[9][4];
#pragma unroll
    for (int j = 0; j < 9; j++)
#pragma unroll
        for (int c = 0; c < 4; c++) o[j][c] = 0.f;

    // tile-fill addressing (256 threads, cp.async 16B x 8 per thread)
    const int krow = tid >> 1, kseg = tid & 1;
    const __half* ksrc0 =
        kp + ((size_t)(b * SS + krow) * HH + h) * DQ + kseg * 32;
    const int vd0 = tid >> 2, vseg = tid & 3;
    const __half* vsrc0 =
        vtp + (((size_t)(b * HH + h)) * DQ + vd0) * SS + vseg * 32;
    const uint32_t sb = (uint32_t)__cvta_generic_to_shared(sm);
    const uint32_t kaddr = sb + (uint32_t)(krow * KSH + kseg * 32) * 2;
    const uint32_t vaddr = sb + (uint32_t)(128 * KSH + vd0 * VSH + vseg * 32) * 2;

#define ISSUE_TILE(T0, STG) do {                                              \
    const __half* _ks = ksrc0 + (size_t)(T0) * (HH * DQ);                     \
    const __half* _vs = vsrc0 + (T0);                                         \
    uint32_t _ko = kaddr + (uint32_t)(STG) * (STAGE_H * 2);                   \
    uint32_t _vo = vaddr + (uint32_t)(STG) * (STAGE_H * 2);                   \
    _Pragma("unroll")                                                         \
    for (int cc = 0; cc < 4; cc++) {                                          \
        int c = (cc + krow) & 3;                                              \
        cpasync16(_ko + c * 16, _ks + c * 8);                                 \
    }                                                                         \
    _Pragma("unroll")                                                         \
    for (int cc = 0; cc < 4; cc++) {                                          \
        int c = (cc + vd0 + vseg) & 3;                                        \
        cpasync16(_vo + c * 16, _vs + c * 8);                                 \
    }                                                                         \
    asm volatile("cp.async.commit_group;" ::: "memory");                      \
} while (0)

    ISSUE_TILE(0, 0);
    int stg = 0;

    for (int t0 = 0; t0 < SS; t0 += 128) {
        asm volatile("cp.async.wait_group 0;" ::: "memory");
        __syncthreads();
        if (t0 + 128 < SS) ISSUE_TILE(t0 + 128, stg ^ 1);

        const __half* Ks = sm + stg * STAGE_H;
        const __half* Vt = sm + stg * STAGE_H + 128 * KSH;

#pragma unroll
        for (int chunk = 0; chunk < 4; chunk++) {
            const int kb = chunk * 32;

            float sj[4][4];
#pragma unroll
            for (int j = 0; j < 4; j++)
#pragma unroll
                for (int c = 0; c < 4; c++) sj[j][c] = 0.f;

#pragma unroll
            for (int s = 0; s < 4; s++) {
#pragma unroll
                for (int j = 0; j < 4; j++) {
                    uint2 bb = *(const uint2*)(Ks + (size_t)(kb + j * 8 + g) * KSH +
                                               s * 16 + 4 * t);
                    uint32_t bf[2] = {bb.x, bb.y};
                    mma16(sj[j], qa[s], bf);
                }
            }

            // online softmax (base 2; scale folded into Q) with skip ballot
            float mx0 = -INFINITY, mx1 = -INFINITY;
#pragma unroll
            for (int j = 0; j < 4; j++) {
                mx0 = fmaxf(mx0, fmaxf(sj[j][0], sj[j][1]));
                mx1 = fmaxf(mx1, fmaxf(sj[j][2], sj[j][3]));
            }
            bool upd = (mx0 > m[0]) || (mx1 > m[1]);
            if (__ballot_sync(0xffffffffu, upd) != 0u) {
                mx0 = fmaxf(mx0, __shfl_xor_sync(0xffffffffu, mx0, 1));
                mx0 = fmaxf(mx0, __shfl_xor_sync(0xffffffffu, mx0, 2));
                mx1 = fmaxf(mx1, __shfl_xor_sync(0xffffffffu, mx1, 1));
                mx1 = fmaxf(mx1, __shfl_xor_sync(0xffffffffu, mx1, 2));
                float mn0 = fmaxf(m[0], mx0);
                float mn1 = fmaxf(m[1], mx1);
                float al0 = ex2f(m[0] - mn0);
                float al1 = ex2f(m[1] - mn1);
                m[0] = mn0;
                m[1] = mn1;
#pragma unroll
                for (int j = 0; j < 9; j++) {
                    o[j][0] *= al0;
                    o[j][1] *= al0;
                    o[j][2] *= al1;
                    o[j][3] *= al1;
                }
            }
#pragma unroll
            for (int j = 0; j < 4; j++) {
                sj[j][0] = ex2f(sj[j][0] - m[0]);
                sj[j][1] = ex2f(sj[j][1] - m[0]);
                sj[j][2] = ex2f(sj[j][2] - m[1]);
                sj[j][3] = ex2f(sj[j][3] - m[1]);
            }

            // O += P @ V ; l += P @ 1 (j==8, ones fragment)
#pragma unroll
            for (int G = 0; G < 2; G++) {
                uint32_t pa[4];
                pa[0] = fh2(sj[2 * G][0], sj[2 * G][1]);
                pa[1] = fh2(sj[2 * G][2], sj[2 * G][3]);
                pa[2] = fh2(sj[2 * G + 1][0], sj[2 * G + 1][1]);
                pa[3] = fh2(sj[2 * G + 1][2], sj[2 * G + 1][3]);
                int kg = chunk * 2 + G;
#pragma unroll
                for (int j = 0; j < 8; j++) {
                    uint2 bb = *(const uint2*)(Vt + (size_t)(j * 8 + g) * VSH +
                                               kg * 16 + 4 * t);
                    uint32_t bf[2] = {bb.x, bb.y};
                    mma16(o[j], pa, bf);
                }
                uint32_t ones[2] = {ONES2, ONES2};
                mma16(o[8], pa, ones);
            }
        }
        stg ^= 1;
    }

    // normalize + store heads (half, phys layout matches final-GEMM perm)
    __half* ob = op + ((size_t)(b * HH + h) * SS + s0) * DQ;
    {
        int rA = rowbase + g;
        float inv0 = 1.f / o[8][0];
        float inv1 = 1.f / o[8][2];
#pragma unroll
        for (int j = 0; j < 8; j++) {
            int cn = j * 8 + t * 2;
            *(uint32_t*)(ob + (size_t)rA * DQ + cn) =
                fh2(o[j][0] * inv0, o[j][1] * inv0);
            *(uint32_t*)(ob + (size_t)(rA + 8) * DQ + cn) =
                fh2(o[j][2] * inv1, o[j][3] * inv1);
        }
    }
}

// ---------------------------------------------------------------- launch
extern "C" void kernel_launch(void* const* d_in, const int* in_sizes, int n_in,
                              void* d_out, int out_size) {
    const float* xq = (const float*)d_in[0];
    const float* xk = (const float*)d_in[1];
    const float* xv = (const float*)d_in[2];
    const float* Qw = (const float*)d_in[3];
    const float* Kw = (const float*)d_in[4];
    const float* Vw = (const float*)d_in[5];
    const float* Wo = (const float*)d_in[6];
    float* out = (float*)d_out;

    __half *pq, *pk, *pvt, *ph;
    cudaGetSymbolAddress((void**)&pq, g_qh);
    cudaGetSymbolAddress((void**)&pk, g_kh);
    cudaGetSymbolAddress((void**)&pvt, g_vt);
    cudaGetSymbolAddress((void**)&ph, g_hh);

    static int attr_done = 0;
    if (!attr_done) {
        cudaFuncSetAttribute(gemm_qkv, cudaFuncAttributeMaxDynamicSharedMemorySize,
                             GE_SMEM);
        cudaFuncSetAttribute(gemm_out, cudaFuncAttributeMaxDynamicSharedMemorySize,
                             GE_SMEM);
        cudaFuncSetAttribute(flash_h, cudaFuncAttributeMaxDynamicSharedMemorySize,
                             FL_SMEM);
        attr_done = 1;
    }

    prep_w<<<64, 256>>>(Qw, Kw, Vw, Wo);

    gemm_qkv<<<dim3(DM / 128, (BB * SS) / 128, 3), 256, GE_SMEM>>>(xq, xk, xv);

    vtrans<<<dim3(SS / 64, HH, BB), 128>>>();

    flash_h<<<dim3(SS / 128, HH, BB), 256, FL_SMEM>>>(pq, pk, pvt, ph);

    gemm_out<<<dim3(DM / 128, (BB * SS) / 128), 256, GE_SMEM>>>(out);
}

// round 16
// speedup vs baseline: 1.0700x; 1.0700x over previous
#include <cuda_runtime.h>
#include <cuda_fp16.h>
#include <math.h>
#include <stdint.h>

#define BB 4
#define HH 8
#define SS 2048
#define DM 512
#define DQ 64

// ---------------------------------------------------------------- utils
__device__ __forceinline__ float ex2f(float x) {
    float y;
    asm("ex2.approx.f32 %0, %1;" : "=f"(y) : "f"(x));
    return y;
}
__device__ __forceinline__ uint32_t fh2(float a, float b) {
    __half2 h = __floats2half2_rn(a, b);
    return *reinterpret_cast<uint32_t*>(&h);
}
// D += A(16x16) @ B(16x8), fp16 inputs, fp32 accum
__device__ __forceinline__ void mma16(float d[4], const uint32_t a[4],
                                      const uint32_t b[2]) {
    asm volatile(
        "mma.sync.aligned.m16n8k16.row.col.f32.f16.f16.f32 "
        "{%0,%1,%2,%3}, {%4,%5,%6,%7}, {%8,%9}, {%0,%1,%2,%3};"
        : "+f"(d[0]), "+f"(d[1]), "+f"(d[2]), "+f"(d[3])
        : "r"(a[0]), "r"(a[1]), "r"(a[2]), "r"(a[3]), "r"(b[0]), "r"(b[1]));
}

// permuted pack of 16 logical halves into fragment order (involution):
// phys = [0,1,8,9,2,3,10,11 | 4,5,12,13,6,7,14,15]
__device__ __forceinline__ void pack16(__half* dst, const float* v) {
    __half2* d2 = reinterpret_cast<__half2*>(dst);
    d2[0] = __floats2half2_rn(v[0], v[1]);
    d2[1] = __floats2half2_rn(v[8], v[9]);
    d2[2] = __floats2half2_rn(v[2], v[3]);
    d2[3] = __floats2half2_rn(v[10], v[11]);
    d2[4] = __floats2half2_rn(v[4], v[5]);
    d2[5] = __floats2half2_rn(v[12], v[13]);
    d2[6] = __floats2half2_rn(v[6], v[7]);
    d2[7] = __floats2half2_rn(v[14], v[15]);
}

// ---------------------------------------------------------------- scratch (half)
__device__ __half g_Wqh[DM * DM];
__device__ __half g_Wkh[DM * DM];
__device__ __half g_Wvh[DM * DM];
__device__ __half g_Woh[DM * DM];
__device__ __half g_qh[BB * SS * DM];   // [b,s,h,dq] permuted-dq
__device__ __half g_kh[BB * SS * DM];
__device__ __half g_vt[BB * SS * DM];   // V transposed [b][h][d][s_perm]
__device__ __half g_hh[BB * SS * DM];   // [b,h,s,dq] == concat view, permuted

// weights -> [n][k] half, k permuted; Wq scaled by 0.125*log2(e)
__global__ void prep_w(const float* __restrict__ Qw, const float* __restrict__ Kw,
                       const float* __restrict__ Vw, const float* __restrict__ Wo) {
    int idx = blockIdx.x * 256 + threadIdx.x;    // 512*32
    int n = idx >> 5;
    int grp = idx & 31;
    int hh = n >> 6, q = n & 63;
    const float SC = 0.125f * 1.4426950408889634f;
    float wq[16], wk[16], wv[16], wo[16];
#pragma unroll
    for (int l = 0; l < 16; l++) {
        int d = grp * 16 + l;
        int src = (hh * DM + d) * DQ + q;
        wq[l] = Qw[src] * SC;
        wk[l] = Kw[src];
        wv[l] = Vw[src];
        wo[l] = Wo[n * DM + d];
    }
    pack16(g_Wqh + n * DM + grp * 16, wq);
    pack16(g_Wkh + n * DM + grp * 16, wk);
    pack16(g_Wvh + n * DM + grp * 16, wv);
    pack16(g_Woh + n * DM + grp * 16, wo);
}

// ---------------------------------------------------------------- GEMM common
#define GSH 48
#define GTW (128 * GSH)
#define GE_SMEM (4 * GTW * 2)
#define TST 136   // transpose staging stride (halves)

// fused projection GEMM: A fp32 (converted+permuted on the fly), B = weights.
// z==0/1 -> half permuted [b,s,h,d]; z==2 -> smem-staged transpose into
// g_vt [b][h][d][s_perm] (same addressing as the former vtrans kernel).
__global__ __launch_bounds__(256, 2) void gemm_qkv(const float* __restrict__ xq,
                                                   const float* __restrict__ xk,
                                                   const float* __restrict__ xv) {
    extern __shared__ __half sg[];
    const int z = blockIdx.z;
    const float* A = (z == 0) ? xq : (z == 1) ? xk : xv;
    const __half* B = (z == 0) ? g_Wqh : (z == 1) ? g_Wkh : g_Wvh;
    __half* C = (z == 0) ? g_qh : g_kh;
    const int N = DM, K = DM;

    const int tid = threadIdx.x;
    const int lane = tid & 31;
    const int wid = tid >> 5;
    const int g = lane >> 2;
    const int t = lane & 3;
    const int wm = wid & 1;
    const int wn = wid >> 1;
    const int m0 = blockIdx.y * 128;
    const int n0 = blockIdx.x * 128;

    const int aRow = tid >> 1;
    const int c0 = tid & 1;

    const float* gAf = A + (size_t)(m0 + aRow) * K;
    const __half* gB = B + (size_t)(n0 + aRow) * K;

    float d[4][4][4];
#pragma unroll
    for (int i = 0; i < 4; i++)
#pragma unroll
        for (int j = 0; j < 4; j++)
#pragma unroll
            for (int c = 0; c < 4; c++) d[i][j][c] = 0.f;

    uint4 la[2], lb[2];
#pragma unroll
    for (int gi = 0; gi < 2; gi++) {
        float4 p0 = *(const float4*)(gAf + gi * 16 + c0 * 4);
        float4 p1 = *(const float4*)(gAf + gi * 16 + c0 * 4 + 8);
        la[gi] = make_uint4(fh2(p0.x, p0.y), fh2(p1.x, p1.y), fh2(p0.z, p0.w),
                            fh2(p1.z, p1.w));
    }
    lb[0] = *(const uint4*)(gB + c0 * 8);
    lb[1] = *(const uint4*)(gB + (c0 + 2) * 8);
    {
        uint4* sA = (uint4*)(sg + aRow * GSH);
        uint4* sB = (uint4*)(sg + 2 * GTW + aRow * GSH);
        sA[c0] = la[0];
        sA[c0 + 2] = la[1];
        sB[c0] = lb[0];
        sB[c0 + 2] = lb[1];
    }
    __syncthreads();

    int buf = 0;
    for (int kt = 32; kt <= K; kt += 32) {
        const bool more = (kt < K);
        if (more) {
#pragma unroll
            for (int gi = 0; gi < 2; gi++) {
                float4 p0 = *(const float4*)(gAf + kt + gi * 16 + c0 * 4);
                float4 p1 = *(const float4*)(gAf + kt + gi * 16 + c0 * 4 + 8);
                la[gi] = make_uint4(fh2(p0.x, p0.y), fh2(p1.x, p1.y),
                                    fh2(p0.z, p0.w), fh2(p1.z, p1.w));
            }
            lb[0] = *(const uint4*)(gB + kt + c0 * 8);
            lb[1] = *(const uint4*)(gB + kt + (c0 + 2) * 8);
        }

        const __half* pA = sg + buf * GTW;
        const __half* pB = sg + 2 * GTW + buf * GTW;
#pragma unroll
        for (int s = 0; s < 2; s++) {
            uint32_t a[4][4], b[4][2];
#pragma unroll
            for (int i = 0; i < 4; i++) {
                int rw = wm * 64 + i * 16 + g;
                uint2 lo = *(const uint2*)(pA + rw * GSH + s * 16 + 4 * t);
                uint2 hi = *(const uint2*)(pA + (rw + 8) * GSH + s * 16 + 4 * t);
                a[i][0] = lo.x;
                a[i][1] = hi.x;
                a[i][2] = lo.y;
                a[i][3] = hi.y;
            }
#pragma unroll
            for (int j = 0; j < 4; j++) {
                int rn = wn * 32 + j * 8 + g;
                uint2 bb = *(const uint2*)(pB + rn * GSH + s * 16 + 4 * t);
                b[j][0] = bb.x;
                b[j][1] = bb.y;
            }
#pragma unroll
            for (int i = 0; i < 4; i++)
#pragma unroll
                for (int j = 0; j < 4; j++) mma16(d[i][j], a[i], b[j]);
        }

        if (more) {
            uint4* qA = (uint4*)(sg + (buf ^ 1) * GTW + aRow * GSH);
            uint4* qB = (uint4*)(sg + 2 * GTW + (buf ^ 1) * GTW + aRow * GSH);
            qA[c0] = la[0];
            qA[c0 + 2] = la[1];
            qB[c0] = lb[0];
            qB[c0 + 2] = lb[1];
        }
        buf ^= 1;
        __syncthreads();   // (final iteration: all smem reads complete here)
    }

    if (z != 2) {
#pragma unroll
        for (int i = 0; i < 4; i++) {
            int r0 = m0 + wm * 64 + i * 16 + g;
#pragma unroll
            for (int j = 0; j < 4; j++) {
                int colh = n0 + (wn * 2 + (j >> 1)) * 16 + 4 * t + 2 * (j & 1);
                *(uint32_t*)(C + (size_t)r0 * N + colh) = fh2(d[i][j][0], d[i][j][1]);
                *(uint32_t*)(C + (size_t)(r0 + 8) * N + colh) =
                    fh2(d[i][j][2], d[i][j][3]);
            }
        }
    } else {
        // V: stage the 128x128 output tile in smem, then coalesced
        // transposed write to g_vt[b][h][d][s_perm].
        __half* Th = sg;   // 128 * TST halves = 34816 B (fits in GE_SMEM)
#pragma unroll
        for (int i = 0; i < 4; i++) {
            int rl = wm * 64 + i * 16 + g;
#pragma unroll
            for (int j = 0; j < 4; j++) {
                int colh = (wn * 2 + (j >> 1)) * 16 + 4 * t + 2 * (j & 1);
                *(uint32_t*)(Th + rl * TST + colh) = fh2(d[i][j][0], d[i][j][1]);
                *(uint32_t*)(Th + (rl + 8) * TST + colh) =
                    fh2(d[i][j][2], d[i][j][3]);
            }
        }
        __syncthreads();

        const int PERM[16] = {0, 1, 8, 9, 2, 3, 10, 11,
                              4, 5, 12, 13, 6, 7, 14, 15};
        int colh2 = tid >> 1, seg = tid & 1;
        int hl = colh2 >> 6, dd = colh2 & 63;
        int bidx = m0 >> 11, srow = m0 & 2047;
        int hg = (n0 >> 6) + hl;
        __half* outp = g_vt + (((size_t)(bidx * HH + hg)) * DQ + dd) * SS +
                       srow + seg * 64;
#pragma unroll
        for (int c8 = 0; c8 < 8; c8++) {
            __half vals[8];
#pragma unroll
            for (int p8 = 0; p8 < 8; p8++) {
                int p = c8 * 8 + p8;
                int k = seg * 64 + (p & ~15) + PERM[p & 15];
                vals[p8] = Th[k * TST + colh2];
            }
            *(uint4*)(outp + c8 * 8) = *(const uint4*)vals;
        }
    }
}

// output projection: A = g_hh (half permuted), B = g_Woh, C fp32
__global__ __launch_bounds__(256, 2) void gemm_out(float* __restrict__ C) {
    extern __shared__ __half sg[];
    const __half* A = g_hh;
    const __half* B = g_Woh;
    const int N = DM, K = DM;

    const int tid = threadIdx.x;
    const int lane = tid & 31;
    const int wid = tid >> 5;
    const int g = lane >> 2;
    const int t = lane & 3;
    const int wm = wid & 1;
    const int wn = wid >> 1;
    const int m0 = blockIdx.y * 128;
    const int n0 = blockIdx.x * 128;

    const int aRow = tid >> 1;
    const int c0 = tid & 1;

    const __half* gA = A + (size_t)(m0 + aRow) * K;
    const __half* gB = B + (size_t)(n0 + aRow) * K;

    float d[4][4][4];
#pragma unroll
    for (int i = 0; i < 4; i++)
#pragma unroll
        for (int j = 0; j < 4; j++)
#pragma unroll
            for (int c = 0; c < 4; c++) d[i][j][c] = 0.f;

    uint4 la[2], lb[2];
    la[0] = *(const uint4*)(gA + c0 * 8);
    la[1] = *(const uint4*)(gA + (c0 + 2) * 8);
    lb[0] = *(const uint4*)(gB + c0 * 8);
    lb[1] = *(const uint4*)(gB + (c0 + 2) * 8);
    {
        uint4* sA = (uint4*)(sg + aRow * GSH);
        uint4* sB = (uint4*)(sg + 2 * GTW + aRow * GSH);
        sA[c0] = la[0];
        sA[c0 + 2] = la[1];
        sB[c0] = lb[0];
        sB[c0 + 2] = lb[1];
    }
    __syncthreads();

    int buf = 0;
    for (int kt = 32; kt <= K; kt += 32) {
        const bool more = (kt < K);
        if (more) {
            la[0] = *(const uint4*)(gA + kt + c0 * 8);
            la[1] = *(const uint4*)(gA + kt + (c0 + 2) * 8);
            lb[0] = *(const uint4*)(gB + kt + c0 * 8);
            lb[1] = *(const uint4*)(gB + kt + (c0 + 2) * 8);
        }

        const __half* pA = sg + buf * GTW;
        const __half* pB = sg + 2 * GTW + buf * GTW;
#pragma unroll
        for (int s = 0; s < 2; s++) {
            uint32_t a[4][4], b[4][2];
#pragma unroll
            for (int i = 0; i < 4; i++) {
                int rw = wm * 64 + i * 16 + g;
                uint2 lo = *(const uint2*)(pA + rw * GSH + s * 16 + 4 * t);
                uint2 hi = *(const uint2*)(pA + (rw + 8) * GSH + s * 16 + 4 * t);
                a[i][0] = lo.x;
                a[i][1] = hi.x;
                a[i][2] = lo.y;
                a[i][3] = hi.y;
            }
#pragma unroll
            for (int j = 0; j < 4; j++) {
                int rn = wn * 32 + j * 8 + g;
                uint2 bb = *(const uint2*)(pB + rn * GSH + s * 16 + 4 * t);
                b[j][0] = bb.x;
                b[j][1] = bb.y;
            }
#pragma unroll
            for (int i = 0; i < 4; i++)
#pragma unroll
                for (int j = 0; j < 4; j++) mma16(d[i][j], a[i], b[j]);
        }

        if (more) {
            uint4* qA = (uint4*)(sg + (buf ^ 1) * GTW + aRow * GSH);
            uint4* qB = (uint4*)(sg + 2 * GTW + (buf ^ 1) * GTW + aRow * GSH);
            qA[c0] = la[0];
            qA[c0 + 2] = la[1];
            qB[c0] = lb[0];
            qB[c0 + 2] = lb[1];
        }
        buf ^= 1;
        __syncthreads();
    }

#pragma unroll
    for (int i = 0; i < 4; i++) {
        int r0 = m0 + wm * 64 + i * 16 + g;
#pragma unroll
        for (int j = 0; j < 4; j++) {
            int cn = n0 + wn * 32 + j * 8 + t * 2;
            *(float2*)(C + (size_t)r0 * N + cn) = make_float2(d[i][j][0], d[i][j][1]);
            *(float2*)(C + (size_t)(r0 + 8) * N + cn) =
                make_float2(d[i][j][2], d[i][j][3]);
        }
    }
}

// ---------------------------------------------------------------- flash (fp16)
// R14 flash (best measured): CTA = (b, h, 128 query rows), 256 threads /
// 8 warps, warp owns 16 rows. Plain LDG tile loads (L1-cacheable), Q in regs,
// 32-key chunks, pre-transposed V, skip-rescale ballot, l via ones-mma.
#define KSH 80
#define VSH 144
#define KS_HALVES (128 * KSH)
#define FL_SMEM ((128 * KSH + 64 * VSH) * 2)
#define ONES2 0x3C003C00u

__global__ __launch_bounds__(256, 2) void flash_h(const __half* __restrict__ qp,
                                                  const __half* __restrict__ kp,
                                                  const __half* __restrict__ vtp,
                                                  __half* __restrict__ op) {
    extern __shared__ __half sm[];
    __half* Ks = sm;
    __half* Vt = sm + KS_HALVES;

    const int tid = threadIdx.x;
    const int lane = tid & 31;
    const int wid = tid >> 5;      // 0..7
    const int g = lane >> 2;
    const int t = lane & 3;
    const int b = blockIdx.z;
    const int h = blockIdx.y;
    const int s0 = blockIdx.x * 128;
    const int rowbase = wid * 16;

    // Q fragments: one 16-row tile per warp
    const __half* gq = qp + ((size_t)(b * SS + s0) * HH + h) * DQ;
    uint32_t qa[4][4];
    {
        const __half* q0 = gq + (size_t)(rowbase + g) * DM;
        const __half* q1 = q0 + 8 * DM;
#pragma unroll
        for (int s = 0; s < 4; s++) {
            uint2 u0 = *(const uint2*)(q0 + s * 16 + 4 * t);
            uint2 u1 = *(const uint2*)(q1 + s * 16 + 4 * t);
            qa[s][0] = u0.x;
            qa[s][1] = u1.x;
            qa[s][2] = u0.y;
            qa[s][3] = u1.y;
        }
    }

    float m[2] = {-INFINITY, -INFINITY};
    float o[9][4];
#pragma unroll
    for (int j = 0; j < 9; j++)
#pragma unroll
        for (int c = 0; c < 4; c++) o[j][c] = 0.f;

    // tile-fill pointers (256 threads)
    const int krow = tid >> 1, kseg = tid & 1;
    const uint4* ksrc0 =
        (const uint4*)(kp + ((size_t)(b * SS + krow) * HH + h) * DQ + kseg * 32);
    uint4* kdst = (uint4*)(Ks + krow * KSH + kseg * 32);
    const int vd = tid >> 2, vseg = tid & 3;
    const uint4* vsrc0 =
        (const uint4*)(vtp + (((size_t)(b * HH + h)) * DQ + vd) * SS + vseg * 32);
    uint4* vdst = (uint4*)(Vt + vd * VSH + vseg * 32);

    for (int t0 = 0; t0 < SS; t0 += 128) {
        __syncthreads();
        const uint4* ksp = ksrc0 + (size_t)t0 * 64;   // t0 * HH*DQ / 8
        const uint4* vsp = vsrc0 + (t0 >> 3);
#pragma unroll
        for (int cc = 0; cc < 4; cc++) {
            int c = (cc + krow) & 3;
            kdst[c] = ksp[c];
        }
#pragma unroll
        for (int cc = 0; cc < 4; cc++) {
            int c = (cc + vd + vseg) & 3;
            vdst[c] = vsp[c];
        }
        __syncthreads();

#pragma unroll
        for (int chunk = 0; chunk < 4; chunk++) {
            const int kb = chunk * 32;

            float sj[4][4];
#pragma unroll
            for (int j = 0; j < 4; j++)
#pragma unroll
                for (int c = 0; c < 4; c++) sj[j][c] = 0.f;

#pragma unroll
            for (int s = 0; s < 4; s++) {
#pragma unroll
                for (int j = 0; j < 4; j++) {
                    uint2 bb = *(const uint2*)(Ks + (size_t)(kb + j * 8 + g) * KSH +
                                               s * 16 + 4 * t);
                    uint32_t bf[2] = {bb.x, bb.y};
                    mma16(sj[j], qa[s], bf);
                }
            }

            // online softmax (base 2; scale folded into Q) with skip ballot
            float mx0 = -INFINITY, mx1 = -INFINITY;
#pragma unroll
            for (int j = 0; j < 4; j++) {
                mx0 = fmaxf(mx0, fmaxf(sj[j][0], sj[j][1]));
                mx1 = fmaxf(mx1, fmaxf(sj[j][2], sj[j][3]));
            }
            bool upd = (mx0 > m[0]) || (mx1 > m[1]);
            if (__ballot_sync(0xffffffffu, upd) != 0u) {
                mx0 = fmaxf(mx0, __shfl_xor_sync(0xffffffffu, mx0, 1));
                mx0 = fmaxf(mx0, __shfl_xor_sync(0xffffffffu, mx0, 2));
                mx1 = fmaxf(mx1, __shfl_xor_sync(0xffffffffu, mx1, 1));
                mx1 = fmaxf(mx1, __shfl_xor_sync(0xffffffffu, mx1, 2));
                float mn0 = fmaxf(m[0], mx0);
                float mn1 = fmaxf(m[1], mx1);
                float al0 = ex2f(m[0] - mn0);
                float al1 = ex2f(m[1] - mn1);
                m[0] = mn0;
                m[1] = mn1;
#pragma unroll
                for (int j = 0; j < 9; j++) {
                    o[j][0] *= al0;
                    o[j][1] *= al0;
                    o[j][2] *= al1;
                    o[j][3] *= al1;
                }
            }
#pragma unroll
            for (int j = 0; j < 4; j++) {
                sj[j][0] = ex2f(sj[j][0] - m[0]);
                sj[j][1] = ex2f(sj[j][1] - m[0]);
                sj[j][2] = ex2f(sj[j][2] - m[1]);
                sj[j][3] = ex2f(sj[j][3] - m[1]);
            }

            // O += P @ V ; l += P @ 1 (j==8, ones fragment)
#pragma unroll
            for (int G = 0; G < 2; G++) {
                uint32_t pa[4];
                pa[0] = fh2(sj[2 * G][0], sj[2 * G][1]);
                pa[1] = fh2(sj[2 * G][2], sj[2 * G][3]);
                pa[2] = fh2(sj[2 * G + 1][0], sj[2 * G + 1][1]);
                pa[3] = fh2(sj[2 * G + 1][2], sj[2 * G + 1][3]);
                int kg = chunk * 2 + G;
#pragma unroll
                for (int j = 0; j < 8; j++) {
                    uint2 bb = *(const uint2*)(Vt + (size_t)(j * 8 + g) * VSH +
                                               kg * 16 + 4 * t);
                    uint32_t bf[2] = {bb.x, bb.y};
                    mma16(o[j], pa, bf);
                }
                uint32_t ones[2] = {ONES2, ONES2};
                mma16(o[8], pa, ones);
            }
        }
    }

    // normalize + store heads (half, phys layout matches final-GEMM perm)
    __half* ob = op + ((size_t)(b * HH + h) * SS + s0) * DQ;
    {
        int rA = rowbase + g;
        float inv0 = 1.f / o[8][0];
        float inv1 = 1.f / o[8][2];
#pragma unroll
        for (int j = 0; j < 8; j++) {
            int cn = j * 8 + t * 2;
            *(uint32_t*)(ob + (size_t)rA * DQ + cn) =
                fh2(o[j][0] * inv0, o[j][1] * inv0);
            *(uint32_t*)(ob + (size_t)(rA + 8) * DQ + cn) =
                fh2(o[j][2] * inv1, o[j][3] * inv1);
        }
    }
}

// ---------------------------------------------------------------- launch
extern "C" void kernel_launch(void* const* d_in, const int* in_sizes, int n_in,
                              void* d_out, int out_size) {
    const float* xq = (const float*)d_in[0];
    const float* xk = (const float*)d_in[1];
    const float* xv = (const float*)d_in[2];
    const float* Qw = (const float*)d_in[3];
    const float* Kw = (const float*)d_in[4];
    const float* Vw = (const float*)d_in[5];
    const float* Wo = (const float*)d_in[6];
    float* out = (float*)d_out;

    __half *pq, *pk, *pvt, *ph;
    cudaGetSymbolAddress((void**)&pq, g_qh);
    cudaGetSymbolAddress((void**)&pk, g_kh);
    cudaGetSymbolAddress((void**)&pvt, g_vt);
    cudaGetSymbolAddress((void**)&ph, g_hh);

    static int attr_done = 0;
    if (!attr_done) {
        cudaFuncSetAttribute(gemm_qkv, cudaFuncAttributeMaxDynamicSharedMemorySize,
                             GE_SMEM);
        cudaFuncSetAttribute(gemm_out, cudaFuncAttributeMaxDynamicSharedMemorySize,
                             GE_SMEM);
        cudaFuncSetAttribute(flash_h, cudaFuncAttributeMaxDynamicSharedMemorySize,
                             FL_SMEM);
        attr_done = 1;
    }

    prep_w<<<64, 256>>>(Qw, Kw, Vw, Wo);

    gemm_qkv<<<dim3(DM / 128, (BB * SS) / 128, 3), 256, GE_SMEM>>>(xq, xk, xv);

    flash_h<<<dim3(SS / 128, HH, BB), 256, FL_SMEM>>>(pq, pk, pvt, ph);

    gemm_out<<<dim3(DM / 128, (BB * SS) / 128), 256, GE_SMEM>>>(out);
}

// round 17
// speedup vs baseline: 1.1014x; 1.0294x over previous
#include <cuda_runtime.h>
#include <cuda_fp16.h>
#include <math.h>
#include <stdint.h>

#define BB 4
#define HH 8
#define SS 2048
#define DM 512
#define DQ 64

// ---------------------------------------------------------------- utils
__device__ __forceinline__ float ex2f(float x) {
    float y;
    asm("ex2.approx.f32 %0, %1;" : "=f"(y) : "f"(x));
    return y;
}
__device__ __forceinline__ uint32_t fh2(float a, float b) {
    __half2 h = __floats2half2_rn(a, b);
    return *reinterpret_cast<uint32_t*>(&h);
}
// packed half2 exp2: cvt two f32 -> half2, one MUFU ex2.f16x2
__device__ __forceinline__ uint32_t ex2h2(float a, float b) {
    uint32_t p = fh2(a, b);
    uint32_t r;
    asm("ex2.approx.f16x2 %0, %1;" : "=r"(r) : "r"(p));
    return r;
}
// D += A(16x16) @ B(16x8), fp16 inputs, fp32 accum
__device__ __forceinline__ void mma16(float d[4], const uint32_t a[4],
                                      const uint32_t b[2]) {
    asm volatile(
        "mma.sync.aligned.m16n8k16.row.col.f32.f16.f16.f32 "
        "{%0,%1,%2,%3}, {%4,%5,%6,%7}, {%8,%9}, {%0,%1,%2,%3};"
        : "+f"(d[0]), "+f"(d[1]), "+f"(d[2]), "+f"(d[3])
        : "r"(a[0]), "r"(a[1]), "r"(a[2]), "r"(a[3]), "r"(b[0]), "r"(b[1]));
}

// permuted pack of 16 logical halves into fragment order (involution):
// phys = [0,1,8,9,2,3,10,11 | 4,5,12,13,6,7,14,15]
__device__ __forceinline__ void pack16(__half* dst, const float* v) {
    __half2* d2 = reinterpret_cast<__half2*>(dst);
    d2[0] = __floats2half2_rn(v[0], v[1]);
    d2[1] = __floats2half2_rn(v[8], v[9]);
    d2[2] = __floats2half2_rn(v[2], v[3]);
    d2[3] = __floats2half2_rn(v[10], v[11]);
    d2[4] = __floats2half2_rn(v[4], v[5]);
    d2[5] = __floats2half2_rn(v[12], v[13]);
    d2[6] = __floats2half2_rn(v[6], v[7]);
    d2[7] = __floats2half2_rn(v[14], v[15]);
}

// ---------------------------------------------------------------- scratch (half)
__device__ __half g_Wqh[DM * DM];
__device__ __half g_Wkh[DM * DM];
__device__ __half g_Wvh[DM * DM];
__device__ __half g_Woh[DM * DM];
__device__ __half g_qh[BB * SS * DM];   // [b,s,h,dq] permuted-dq
__device__ __half g_kh[BB * SS * DM];
__device__ __half g_vt[BB * SS * DM];   // V transposed [b][h][d][s_perm]
__device__ __half g_hh[BB * SS * DM];   // [b,h,s,dq] == concat view, permuted

// weights -> [n][k] half, k permuted; Wq scaled by 0.125*log2(e)
__global__ void prep_w(const float* __restrict__ Qw, const float* __restrict__ Kw,
                       const float* __restrict__ Vw, const float* __restrict__ Wo) {
    int idx = blockIdx.x * 256 + threadIdx.x;    // 512*32
    int n = idx >> 5;
    int grp = idx & 31;
    int hh = n >> 6, q = n & 63;
    const float SC = 0.125f * 1.4426950408889634f;
    float wq[16], wk[16], wv[16], wo[16];
#pragma unroll
    for (int l = 0; l < 16; l++) {
        int d = grp * 16 + l;
        int src = (hh * DM + d) * DQ + q;
        wq[l] = Qw[src] * SC;
        wk[l] = Kw[src];
        wv[l] = Vw[src];
        wo[l] = Wo[n * DM + d];
    }
    pack16(g_Wqh + n * DM + grp * 16, wq);
    pack16(g_Wkh + n * DM + grp * 16, wk);
    pack16(g_Wvh + n * DM + grp * 16, wv);
    pack16(g_Woh + n * DM + grp * 16, wo);
}

// ---------------------------------------------------------------- GEMM common
#define GSH 48
#define GTW (128 * GSH)
#define GE_SMEM (4 * GTW * 2)
#define TST 136   // transpose staging stride (halves)

// fused projection GEMM: A fp32 (converted+permuted on the fly), B = weights.
// z==0/1 -> half permuted [b,s,h,d]; z==2 -> smem-staged transpose into
// g_vt [b][h][d][s_perm].
__global__ __launch_bounds__(256, 2) void gemm_qkv(const float* __restrict__ xq,
                                                   const float* __restrict__ xk,
                                                   const float* __restrict__ xv) {
    extern __shared__ __half sg[];
    const int z = blockIdx.z;
    const float* A = (z == 0) ? xq : (z == 1) ? xk : xv;
    const __half* B = (z == 0) ? g_Wqh : (z == 1) ? g_Wkh : g_Wvh;
    __half* C = (z == 0) ? g_qh : g_kh;
    const int N = DM, K = DM;

    const int tid = threadIdx.x;
    const int lane = tid & 31;
    const int wid = tid >> 5;
    const int g = lane >> 2;
    const int t = lane & 3;
    const int wm = wid & 1;
    const int wn = wid >> 1;
    const int m0 = blockIdx.y * 128;
    const int n0 = blockIdx.x * 128;

    const int aRow = tid >> 1;
    const int c0 = tid & 1;

    const float* gAf = A + (size_t)(m0 + aRow) * K;
    const __half* gB = B + (size_t)(n0 + aRow) * K;

    float d[4][4][4];
#pragma unroll
    for (int i = 0; i < 4; i++)
#pragma unroll
        for (int j = 0; j < 4; j++)
#pragma unroll
            for (int c = 0; c < 4; c++) d[i][j][c] = 0.f;

    uint4 la[2], lb[2];
#pragma unroll
    for (int gi = 0; gi < 2; gi++) {
        float4 p0 = *(const float4*)(gAf + gi * 16 + c0 * 4);
        float4 p1 = *(const float4*)(gAf + gi * 16 + c0 * 4 + 8);
        la[gi] = make_uint4(fh2(p0.x, p0.y), fh2(p1.x, p1.y), fh2(p0.z, p0.w),
                            fh2(p1.z, p1.w));
    }
    lb[0] = *(const uint4*)(gB + c0 * 8);
    lb[1] = *(const uint4*)(gB + (c0 + 2) * 8);
    {
        uint4* sA = (uint4*)(sg + aRow * GSH);
        uint4* sB = (uint4*)(sg + 2 * GTW + aRow * GSH);
        sA[c0] = la[0];
        sA[c0 + 2] = la[1];
        sB[c0] = lb[0];
        sB[c0 + 2] = lb[1];
    }
    __syncthreads();

    int buf = 0;
    for (int kt = 32; kt <= K; kt += 32) {
        const bool more = (kt < K);
        if (more) {
#pragma unroll
            for (int gi = 0; gi < 2; gi++) {
                float4 p0 = *(const float4*)(gAf + kt + gi * 16 + c0 * 4);
                float4 p1 = *(const float4*)(gAf + kt + gi * 16 + c0 * 4 + 8);
                la[gi] = make_uint4(fh2(p0.x, p0.y), fh2(p1.x, p1.y),
                                    fh2(p0.z, p0.w), fh2(p1.z, p1.w));
            }
            lb[0] = *(const uint4*)(gB + kt + c0 * 8);
            lb[1] = *(const uint4*)(gB + kt + (c0 + 2) * 8);
        }

        const __half* pA = sg + buf * GTW;
        const __half* pB = sg + 2 * GTW + buf * GTW;
#pragma unroll
        for (int s = 0; s < 2; s++) {
            uint32_t a[4][4], b[4][2];
#pragma unroll
            for (int i = 0; i < 4; i++) {
                int rw = wm * 64 + i * 16 + g;
                uint2 lo = *(const uint2*)(pA + rw * GSH + s * 16 + 4 * t);
                uint2 hi = *(const uint2*)(pA + (rw + 8) * GSH + s * 16 + 4 * t);
                a[i][0] = lo.x;
                a[i][1] = hi.x;
                a[i][2] = lo.y;
                a[i][3] = hi.y;
            }
#pragma unroll
            for (int j = 0; j < 4; j++) {
                int rn = wn * 32 + j * 8 + g;
                uint2 bb = *(const uint2*)(pB + rn * GSH + s * 16 + 4 * t);
                b[j][0] = bb.x;
                b[j][1] = bb.y;
            }
#pragma unroll
            for (int i = 0; i < 4; i++)
#pragma unroll
                for (int j = 0; j < 4; j++) mma16(d[i][j], a[i], b[j]);
        }

        if (more) {
            uint4* qA = (uint4*)(sg + (buf ^ 1) * GTW + aRow * GSH);
            uint4* qB = (uint4*)(sg + 2 * GTW + (buf ^ 1) * GTW + aRow * GSH);
            qA[c0] = la[0];
            qA[c0 + 2] = la[1];
            qB[c0] = lb[0];
            qB[c0 + 2] = lb[1];
        }
        buf ^= 1;
        __syncthreads();
    }

    if (z != 2) {
#pragma unroll
        for (int i = 0; i < 4; i++) {
            int r0 = m0 + wm * 64 + i * 16 + g;
#pragma unroll
            for (int j = 0; j < 4; j++) {
                int colh = n0 + (wn * 2 + (j >> 1)) * 16 + 4 * t + 2 * (j & 1);
                *(uint32_t*)(C + (size_t)r0 * N + colh) = fh2(d[i][j][0], d[i][j][1]);
                *(uint32_t*)(C + (size_t)(r0 + 8) * N + colh) =
                    fh2(d[i][j][2], d[i][j][3]);
            }
        }
    } else {
        // V: stage the 128x128 output tile in smem, then coalesced
        // transposed write to g_vt[b][h][d][s_perm].
        __half* Th = sg;
#pragma unroll
        for (int i = 0; i < 4; i++) {
            int rl = wm * 64 + i * 16 + g;
#pragma unroll
            for (int j = 0; j < 4; j++) {
                int colh = (wn * 2 + (j >> 1)) * 16 + 4 * t + 2 * (j & 1);
                *(uint32_t*)(Th + rl * TST + colh) = fh2(d[i][j][0], d[i][j][1]);
                *(uint32_t*)(Th + (rl + 8) * TST + colh) =
                    fh2(d[i][j][2], d[i][j][3]);
            }
        }
        __syncthreads();

        const int PERM[16] = {0, 1, 8, 9, 2, 3, 10, 11,
                              4, 5, 12, 13, 6, 7, 14, 15};
        int colh2 = tid >> 1, seg = tid & 1;
        int hl = colh2 >> 6, dd = colh2 & 63;
        int bidx = m0 >> 11, srow = m0 & 2047;
        int hg = (n0 >> 6) + hl;
        __half* outp = g_vt + (((size_t)(bidx * HH + hg)) * DQ + dd) * SS +
                       srow + seg * 64;
#pragma unroll
        for (int c8 = 0; c8 < 8; c8++) {
            __half vals[8];
#pragma unroll
            for (int p8 = 0; p8 < 8; p8++) {
                int p = c8 * 8 + p8;
                int k = seg * 64 + (p & ~15) + PERM[p & 15];
                vals[p8] = Th[k * TST + colh2];
            }
            *(uint4*)(outp + c8 * 8) = *(const uint4*)vals;
        }
    }
}

// output projection: A = g_hh (half permuted), B = g_Woh, C fp32
__global__ __launch_bounds__(256, 2) void gemm_out(float* __restrict__ C) {
    extern __shared__ __half sg[];
    const __half* A = g_hh;
    const __half* B = g_Woh;
    const int N = DM, K = DM;

    const int tid = threadIdx.x;
    const int lane = tid & 31;
    const int wid = tid >> 5;
    const int g = lane >> 2;
    const int t = lane & 3;
    const int wm = wid & 1;
    const int wn = wid >> 1;
    const int m0 = blockIdx.y * 128;
    const int n0 = blockIdx.x * 128;

    const int aRow = tid >> 1;
    const int c0 = tid & 1;

    const __half* gA = A + (size_t)(m0 + aRow) * K;
    const __half* gB = B + (size_t)(n0 + aRow) * K;

    float d[4][4][4];
#pragma unroll
    for (int i = 0; i < 4; i++)
#pragma unroll
        for (int j = 0; j < 4; j++)
#pragma unroll
            for (int c = 0; c < 4; c++) d[i][j][c] = 0.f;

    uint4 la[2], lb[2];
    la[0] = *(const uint4*)(gA + c0 * 8);
    la[1] = *(const uint4*)(gA + (c0 + 2) * 8);
    lb[0] = *(const uint4*)(gB + c0 * 8);
    lb[1] = *(const uint4*)(gB + (c0 + 2) * 8);
    {
        uint4* sA = (uint4*)(sg + aRow * GSH);
        uint4* sB = (uint4*)(sg + 2 * GTW + aRow * GSH);
        sA[c0] = la[0];
        sA[c0 + 2] = la[1];
        sB[c0] = lb[0];
        sB[c0 + 2] = lb[1];
    }
    __syncthreads();

    int buf = 0;
    for (int kt = 32; kt <= K; kt += 32) {
        const bool more = (kt < K);
        if (more) {
            la[0] = *(const uint4*)(gA + kt + c0 * 8);
            la[1] = *(const uint4*)(gA + kt + (c0 + 2) * 8);
            lb[0] = *(const uint4*)(gB + kt + c0 * 8);
            lb[1] = *(const uint4*)(gB + kt + (c0 + 2) * 8);
        }

        const __half* pA = sg + buf * GTW;
        const __half* pB = sg + 2 * GTW + buf * GTW;
#pragma unroll
        for (int s = 0; s < 2; s++) {
            uint32_t a[4][4], b[4][2];
#pragma unroll
            for (int i = 0; i < 4; i++) {
                int rw = wm * 64 + i * 16 + g;
                uint2 lo = *(const uint2*)(pA + rw * GSH + s * 16 + 4 * t);
                uint2 hi = *(const uint2*)(pA + (rw + 8) * GSH + s * 16 + 4 * t);
                a[i][0] = lo.x;
                a[i][1] = hi.x;
                a[i][2] = lo.y;
                a[i][3] = hi.y;
            }
#pragma unroll
            for (int j = 0; j < 4; j++) {
                int rn = wn * 32 + j * 8 + g;
                uint2 bb = *(const uint2*)(pB + rn * GSH + s * 16 + 4 * t);
                b[j][0] = bb.x;
                b[j][1] = bb.y;
            }
#pragma unroll
            for (int i = 0; i < 4; i++)
#pragma unroll
                for (int j = 0; j < 4; j++) mma16(d[i][j], a[i], b[j]);
        }

        if (more) {
            uint4* qA = (uint4*)(sg + (buf ^ 1) * GTW + aRow * GSH);
            uint4* qB = (uint4*)(sg + 2 * GTW + (buf ^ 1) * GTW + aRow * GSH);
            qA[c0] = la[0];
            qA[c0 + 2] = la[1];
            qB[c0] = lb[0];
            qB[c0 + 2] = lb[1];
        }
        buf ^= 1;
        __syncthreads();
    }

#pragma unroll
    for (int i = 0; i < 4; i++) {
        int r0 = m0 + wm * 64 + i * 16 + g;
#pragma unroll
        for (int j = 0; j < 4; j++) {
            int cn = n0 + wn * 32 + j * 8 + t * 2;
            *(float2*)(C + (size_t)r0 * N + cn) = make_float2(d[i][j][0], d[i][j][1]);
            *(float2*)(C + (size_t)(r0 + 8) * N + cn) =
                make_float2(d[i][j][2], d[i][j][3]);
        }
    }
}

// ---------------------------------------------------------------- flash (fp16)
// CTA = (b, h, 128 query rows), 256 threads / 8 warps, warp owns 16 rows.
// Softmax exponentials via ex2.approx.f16x2 (halves MUFU load; output is
// fp16 for P@V anyway). Q in regs, 32-key chunks, pre-transposed V,
// skip-rescale ballot, l via ones-mma.
#define KSH 80
#define VSH 144
#define KS_HALVES (128 * KSH)
#define FL_SMEM ((128 * KSH + 64 * VSH) * 2)
#define ONES2 0x3C003C00u

__global__ __launch_bounds__(256, 2) void flash_h(const __half* __restrict__ qp,
                                                  const __half* __restrict__ kp,
                                                  const __half* __restrict__ vtp,
                                                  __half* __restrict__ op) {
    extern __shared__ __half sm[];
    __half* Ks = sm;
    __half* Vt = sm + KS_HALVES;

    const int tid = threadIdx.x;
    const int lane = tid & 31;
    const int wid = tid >> 5;      // 0..7
    const int g = lane >> 2;
    const int t = lane & 3;
    const int b = blockIdx.z;
    const int h = blockIdx.y;
    const int s0 = blockIdx.x * 128;
    const int rowbase = wid * 16;

    // Q fragments: one 16-row tile per warp
    const __half* gq = qp + ((size_t)(b * SS + s0) * HH + h) * DQ;
    uint32_t qa[4][4];
    {
        const __half* q0 = gq + (size_t)(rowbase + g) * DM;
        const __half* q1 = q0 + 8 * DM;
#pragma unroll
        for (int s = 0; s < 4; s++) {
            uint2 u0 = *(const uint2*)(q0 + s * 16 + 4 * t);
            uint2 u1 = *(const uint2*)(q1 + s * 16 + 4 * t);
            qa[s][0] = u0.x;
            qa[s][1] = u1.x;
            qa[s][2] = u0.y;
            qa[s][3] = u1.y;
        }
    }

    float m[2] = {-INFINITY, -INFINITY};
    float o[9][4];
#pragma unroll
    for (int j = 0; j < 9; j++)
#pragma unroll
        for (int c = 0; c < 4; c++) o[j][c] = 0.f;

    // tile-fill pointers (256 threads)
    const int krow = tid >> 1, kseg = tid & 1;
    const uint4* ksrc0 =
        (const uint4*)(kp + ((size_t)(b * SS + krow) * HH + h) * DQ + kseg * 32);
    uint4* kdst = (uint4*)(Ks + krow * KSH + kseg * 32);
    const int vd = tid >> 2, vseg = tid & 3;
    const uint4* vsrc0 =
        (const uint4*)(vtp + (((size_t)(b * HH + h)) * DQ + vd) * SS + vseg * 32);
    uint4* vdst = (uint4*)(Vt + vd * VSH + vseg * 32);

    for (int t0 = 0; t0 < SS; t0 += 128) {
        __syncthreads();
        const uint4* ksp = ksrc0 + (size_t)t0 * 64;   // t0 * HH*DQ / 8
        const uint4* vsp = vsrc0 + (t0 >> 3);
#pragma unroll
        for (int cc = 0; cc < 4; cc++) {
            int c = (cc + krow) & 3;
            kdst[c] = ksp[c];
        }
#pragma unroll
        for (int cc = 0; cc < 4; cc++) {
            int c = (cc + vd + vseg) & 3;
            vdst[c] = vsp[c];
        }
        __syncthreads();

#pragma unroll
        for (int chunk = 0; chunk < 4; chunk++) {
            const int kb = chunk * 32;

            float sj[4][4];
#pragma unroll
            for (int j = 0; j < 4; j++)
#pragma unroll
                for (int c = 0; c < 4; c++) sj[j][c] = 0.f;

#pragma unroll
            for (int s = 0; s < 4; s++) {
#pragma unroll
                for (int j = 0; j < 4; j++) {
                    uint2 bb = *(const uint2*)(Ks + (size_t)(kb + j * 8 + g) * KSH +
                                               s * 16 + 4 * t);
                    uint32_t bf[2] = {bb.x, bb.y};
                    mma16(sj[j], qa[s], bf);
                }
            }

            // online softmax (base 2; scale folded into Q) with skip ballot
            float mx0 = -INFINITY, mx1 = -INFINITY;
#pragma unroll
            for (int j = 0; j < 4; j++) {
                mx0 = fmaxf(mx0, fmaxf(sj[j][0], sj[j][1]));
                mx1 = fmaxf(mx1, fmaxf(sj[j][2], sj[j][3]));
            }
            bool upd = (mx0 > m[0]) || (mx1 > m[1]);
            if (__ballot_sync(0xffffffffu, upd) != 0u) {
                mx0 = fmaxf(mx0, __shfl_xor_sync(0xffffffffu, mx0, 1));
                mx0 = fmaxf(mx0, __shfl_xor_sync(0xffffffffu, mx0, 2));
                mx1 = fmaxf(mx1, __shfl_xor_sync(0xffffffffu, mx1, 1));
                mx1 = fmaxf(mx1, __shfl_xor_sync(0xffffffffu, mx1, 2));
                float mn0 = fmaxf(m[0], mx0);
                float mn1 = fmaxf(m[1], mx1);
                float al0 = ex2f(m[0] - mn0);
                float al1 = ex2f(m[1] - mn1);
                m[0] = mn0;
                m[1] = mn1;
#pragma unroll
                for (int j = 0; j < 9; j++) {
                    o[j][0] *= al0;
                    o[j][1] *= al0;
                    o[j][2] *= al1;
                    o[j][3] *= al1;
                }
            }

            // exp + pack fused: half2 exponentials (P fragment directly)
            // O += P @ V ; l += P @ 1 (j==8, ones fragment)
#pragma unroll
            for (int G = 0; G < 2; G++) {
                uint32_t pa[4];
                pa[0] = ex2h2(sj[2 * G][0] - m[0], sj[2 * G][1] - m[0]);
                pa[1] = ex2h2(sj[2 * G][2] - m[1], sj[2 * G][3] - m[1]);
                pa[2] = ex2h2(sj[2 * G + 1][0] - m[0], sj[2 * G + 1][1] - m[0]);
                pa[3] = ex2h2(sj[2 * G + 1][2] - m[1], sj[2 * G + 1][3] - m[1]);
                int kg = chunk * 2 + G;
#pragma unroll
                for (int j = 0; j < 8; j++) {
                    uint2 bb = *(const uint2*)(Vt + (size_t)(j * 8 + g) * VSH +
                                               kg * 16 + 4 * t);
                    uint32_t bf[2] = {bb.x, bb.y};
                    mma16(o[j], pa, bf);
                }
                uint32_t ones[2] = {ONES2, ONES2};
                mma16(o[8], pa, ones);
            }
        }
    }

    // normalize + store heads (half, phys layout matches final-GEMM perm)
    __half* ob = op + ((size_t)(b * HH + h) * SS + s0) * DQ;
    {
        int rA = rowbase + g;
        float inv0 = 1.f / o[8][0];
        float inv1 = 1.f / o[8][2];
#pragma unroll
        for (int j = 0; j < 8; j++) {
            int cn = j * 8 + t * 2;
            *(uint32_t*)(ob + (size_t)rA * DQ + cn) =
                fh2(o[j][0] * inv0, o[j][1] * inv0);
            *(uint32_t*)(ob + (size_t)(rA + 8) * DQ + cn) =
                fh2(o[j][2] * inv1, o[j][3] * inv1);
        }
    }
}

// ---------------------------------------------------------------- launch
extern "C" void kernel_launch(void* const* d_in, const int* in_sizes, int n_in,
                              void* d_out, int out_size) {
    const float* xq = (const float*)d_in[0];
    const float* xk = (const float*)d_in[1];
    const float* xv = (const float*)d_in[2];
    const float* Qw = (const float*)d_in[3];
    const float* Kw = (const float*)d_in[4];
    const float* Vw = (const float*)d_in[5];
    const float* Wo = (const float*)d_in[6];
    float* out = (float*)d_out;

    __half *pq, *pk, *pvt, *ph;
    cudaGetSymbolAddress((void**)&pq, g_qh);
    cudaGetSymbolAddress((void**)&pk, g_kh);
    cudaGetSymbolAddress((void**)&pvt, g_vt);
    cudaGetSymbolAddress((void**)&ph, g_hh);

    static int attr_done = 0;
    if (!attr_done) {
        cudaFuncSetAttribute(gemm_qkv, cudaFuncAttributeMaxDynamicSharedMemorySize,
                             GE_SMEM);
        cudaFuncSetAttribute(gemm_out, cudaFuncAttributeMaxDynamicSharedMemorySize,
                             GE_SMEM);
        cudaFuncSetAttribute(flash_h, cudaFuncAttributeMaxDynamicSharedMemorySize,
                             FL_SMEM);
        attr_done = 1;
    }

    prep_w<<<64, 256>>>(Qw, Kw, Vw, Wo);

    gemm_qkv<<<dim3(DM / 128, (BB * SS) / 128, 3), 256, GE_SMEM>>>(xq, xk, xv);

    flash_h<<<dim3(SS / 128, HH, BB), 256, FL_SMEM>>>(pq, pk, pvt, ph);

    gemm_out<<<dim3(DM / 128, (BB * SS) / 128), 256, GE_SMEM>>>(out);
}